// round 15
// baseline (speedup 1.0000x reference)
#include <cuda_runtime.h>
#include <cstdint>

#define NROWS 4096
#define TWO_N 8192
#define DDIM  64
#define BM 128
#define NPAIRS 2080            // 2016 strict upper pairs + 64 diagonal
#define NSTRICT 2016
#define INV_T 20.0f
#define PRESCALE 5.3715827f    // sqrt(20 * log2(e)); dot of scaled = ex2 exponent

// sim smem layout
#define OFF_A    0             // 128x64 bf16 swizzled (16KB)
#define OFF_B    16384         // 16KB
#define OFF_LABR 32768         // 128 ints
#define OFF_LABC 33280         // 128 ints
#define SMEM_BYTES 33792

__device__ __align__(128) uint2 g_feat[TWO_N * 16];   // prescaled bf16, 128B rows
__device__ float g_pt[TWO_N];                          // Ng partials (masked sums)
__device__ float g_pos[NROWS];
__device__ int   g_cnt[64];

static __device__ __forceinline__ uint32_t smem_u32(const void* p) {
    uint32_t a;
    asm("{ .reg .u64 t; cvta.to.shared.u64 t, %1; cvt.u32.u64 %0, t; }" : "=r"(a) : "l"(p));
    return a;
}
static __device__ __forceinline__ float ex2f(float x) {
    float r; asm("ex2.approx.f32 %0, %1;" : "=f"(r) : "f"(x)); return r;
}
static __device__ __forceinline__ uint32_t bf16pack(float lo, float hi) {
    uint32_t r; asm("cvt.rn.bf16x2.f32 %0, %1, %2;" : "=r"(r) : "f"(hi), "f"(lo)); return r;
}
static __device__ __forceinline__ void cpa16(uint32_t dst, const void* src) {
    asm volatile("cp.async.cg.shared.global [%0], [%1], 16;" :: "r"(dst), "l"(src));
}
#define CP_COMMIT() asm volatile("cp.async.commit_group;" ::: "memory")
#define CP_WAIT0()  asm volatile("cp.async.wait_group 0;" ::: "memory")

#define LDSM4(r0, r1, r2, r3, addr) \
    asm volatile("ldmatrix.sync.aligned.m8n8.x4.shared.b16 {%0,%1,%2,%3}, [%4];" \
                 : "=r"(r0), "=r"(r1), "=r"(r2), "=r"(r3) : "r"(addr))

#define MMA16816(d, a, b0, b1) \
    asm volatile("mma.sync.aligned.m16n8k16.row.col.f32.bf16.bf16.f32 " \
                 "{%0,%1,%2,%3}, {%4,%5,%6,%7}, {%8,%9}, {%0,%1,%2,%3};" \
                 : "+f"((d)[0]), "+f"((d)[1]), "+f"((d)[2]), "+f"((d)[3]) \
                 : "r"((a)[0]), "r"((a)[1]), "r"((a)[2]), "r"((a)[3]), "r"(b0), "r"(b1))

// ---- prep: blocks 0..255 convert 16 rows each, pos dots, zero g_pt slice;
//      block 256: hist + out zero ----
__global__ void __launch_bounds__(256)
prep_kernel(const float* __restrict__ f1, const float* __restrict__ f2,
            const int* __restrict__ label, float* __restrict__ out) {
    const int tid = threadIdx.x;
    const int b = blockIdx.x;
    if (b < 256) {
        int r = b * 16 + (tid >> 4);         // global row 0..4095
        int q = tid & 15;                    // float4 slot
        float4 v1 = ((const float4*)(f1 + r * DDIM))[q];
        float4 v2 = ((const float4*)(f2 + r * DDIM))[q];
        g_feat[r * 16 + q] =
            make_uint2(bf16pack(v1.x * PRESCALE, v1.y * PRESCALE),
                       bf16pack(v1.z * PRESCALE, v1.w * PRESCALE));
        g_feat[(r + NROWS) * 16 + q] =
            make_uint2(bf16pack(v2.x * PRESCALE, v2.y * PRESCALE),
                       bf16pack(v2.z * PRESCALE, v2.w * PRESCALE));
        float d = v1.x * v2.x + v1.y * v2.y + v1.z * v2.z + v1.w * v2.w;
        d += __shfl_xor_sync(0xffffffffu, d, 1);
        d += __shfl_xor_sync(0xffffffffu, d, 2);
        d += __shfl_xor_sync(0xffffffffu, d, 4);
        d += __shfl_xor_sync(0xffffffffu, d, 8);
        if (q == 0) g_pos[r] = __expf(d * INV_T);
        if (tid < 32) g_pt[b * 32 + tid] = 0.f;
    } else {
        __shared__ int h[64];
        if (tid < 64) h[tid] = 0;
        __syncthreads();
        for (int i = tid; i < NROWS; i += 256) atomicAdd(&h[label[i] & 63], 1);
        __syncthreads();
        if (tid < 64) g_cnt[tid] = h[tid];
        if (tid == 0) out[0] = 0.f;
    }
}

// ---- sim: strict pairs first; Ng-direct masked sums; deferred col reduce ----
__global__ void __launch_bounds__(256, 3)
sim_kernel(const int* __restrict__ label) {
    extern __shared__ __align__(1024) char smem[];
    const uint32_t sb = smem_u32(smem);
    const int tid  = threadIdx.x;
    const int lane = tid & 31;
    const int wid  = tid >> 5;
    const int warpM = wid >> 1;
    const int warpN = wid & 1;

    // bid -> (ti, tj): strict pairs (ti<tj) for bid<2016, diagonal after
    const int t = blockIdx.x;
    int ti, tj;
    if (t < NSTRICT) {
        ti = (int)(63.5f - sqrtf(63.5f * 63.5f - 2.0f * (float)t));
        while (63 * ti - ti * (ti - 1) / 2 > t) ti--;
        while (63 * (ti + 1) - (ti + 1) * ti / 2 <= t) ti++;
        tj = ti + 1 + (t - (63 * ti - ti * (ti - 1) / 2));
    } else {
        ti = tj = t - NSTRICT;
    }
    const int row0 = ti * BM;
    const int col0 = tj * BM;
    const bool offdiag = (t < NSTRICT);

    // prologue: A (block ti), B (block tj), label slices
    {
        const char* gb = (const char*)g_feat;
#pragma unroll
        for (int it = 0; it < 4; it++) {
            int s = it * 256 + tid;
            int r = s >> 3, c = s & 7;
            uint32_t sw = (uint32_t)((c * 16) ^ ((r & 7) << 4));
            cpa16(sb + OFF_A + r * 128 + sw, gb + (size_t)(row0 + r) * 128 + c * 16);
            cpa16(sb + OFF_B + r * 128 + sw, gb + (size_t)(col0 + r) * 128 + c * 16);
        }
        if (tid < 32) cpa16(sb + OFF_LABR + tid * 16, label + (ti & 31) * 128 + tid * 4);
        else if (tid < 64) cpa16(sb + OFF_LABC + (tid - 32) * 16,
                                 label + (tj & 31) * 128 + (tid - 32) * 4);
        CP_COMMIT();
    }

    const int kaA = (lane >> 4) * 16;
    const int kbB = ((lane >> 3) & 1) * 16;

    CP_WAIT0();
    __syncthreads();

    const int* labr = (const int*)(smem + OFF_LABR);
    const int* labc = (const int*)(smem + OFF_LABC);
    int labR[4];
#pragma unroll
    for (int mb = 0; mb < 2; mb++)
#pragma unroll
        for (int h = 0; h < 2; h++)
            labR[mb * 2 + h] = labr[warpM * 32 + mb * 16 + (lane >> 2) + h * 8];

    float tot[4] = {0.f, 0.f, 0.f, 0.f};
    float v[16];                       // col partials: word 2*s+c, s = qq*2+nb
#pragma unroll
    for (int i = 0; i < 16; i++) v[i] = 0.f;

#pragma unroll
    for (int qq = 0; qq < 4; qq++) {
        const int nbase = warpN * 64 + qq * 16;
        const int nn = nbase + (lane & 7) + ((lane >> 4) & 1) * 8;

        float acc[2][2][4];
#pragma unroll
        for (int mb = 0; mb < 2; mb++)
#pragma unroll
            for (int nb = 0; nb < 2; nb++)
#pragma unroll
                for (int e = 0; e < 4; e++) acc[mb][nb][e] = 0.f;

#pragma unroll
        for (int kc = 0; kc < 4; kc++) {
            uint32_t a[2][4];
#pragma unroll
            for (int mb = 0; mb < 2; mb++) {
                int rowA = warpM * 32 + mb * 16 + (lane & 7) + ((lane >> 3) & 1) * 8;
                uint32_t addr = sb + OFF_A + rowA * 128
                              + ((kc * 32 + kaA) ^ ((rowA & 7) << 4));
                LDSM4(a[mb][0], a[mb][1], a[mb][2], a[mb][3], addr);
            }
            uint32_t b0, b1, b2, b3;
            uint32_t addr = sb + OFF_B + nn * 128
                          + ((kc * 32 + kbB) ^ ((nn & 7) << 4));
            LDSM4(b0, b1, b2, b3, addr);
#pragma unroll
            for (int mb = 0; mb < 2; mb++) {
                MMA16816(acc[mb][0], a[mb], b0, b1);
                MMA16816(acc[mb][1], a[mb], b2, b3);
            }
        }

        // epilogue: exp + masked (Ng-direct) row/col accumulation
#pragma unroll
        for (int nb = 0; nb < 2; nb++) {
            const int s2 = (qq * 2 + nb) * 2;
            int2 lb2 = *(const int2*)(labc + nbase + nb * 8 + (lane & 3) * 2);
#pragma unroll
            for (int mb = 0; mb < 2; mb++)
#pragma unroll
                for (int h = 0; h < 2; h++) {
                    float e0 = ex2f(acc[mb][nb][2 * h]);
                    float e1 = ex2f(acc[mb][nb][2 * h + 1]);
                    float z0 = (lb2.x == labR[mb * 2 + h]) ? 0.f : e0;
                    float z1 = (lb2.y == labR[mb * 2 + h]) ? 0.f : e1;
                    tot[mb * 2 + h] += z0 + z1;
                    v[s2]     += z0;
                    v[s2 + 1] += z1;
                }
        }
    }

    // row path: quad reduce + atomic add
#pragma unroll
    for (int i = 0; i < 4; i++) {
        float tv = tot[i];
        tv += __shfl_xor_sync(0xffffffffu, tv, 1);
        tv += __shfl_xor_sync(0xffffffffu, tv, 2);
        if ((lane & 3) == 0) {
            int grow = row0 + warpM * 32 + (i >> 1) * 16 + (lane >> 2) + (i & 1) * 8;
            atomicAdd(&g_pt[grow], tv);
        }
    }

    // col path (offdiag only): butterfly transpose-reduce over lane groups
    if (offdiag) {
        const bool u1 = (lane & 4) != 0;
#pragma unroll
        for (int i = 0; i < 8; i++) {
            float send = u1 ? v[i] : v[i + 8];
            float recv = __shfl_xor_sync(0xffffffffu, send, 4);
            v[i] = (u1 ? v[i + 8] : v[i]) + recv;
        }
        const bool u2 = (lane & 8) != 0;
#pragma unroll
        for (int i = 0; i < 4; i++) {
            float send = u2 ? v[i] : v[i + 4];
            float recv = __shfl_xor_sync(0xffffffffu, send, 8);
            v[i] = (u2 ? v[i + 4] : v[i]) + recv;
        }
        const bool u3 = (lane & 16) != 0;
#pragma unroll
        for (int i = 0; i < 2; i++) {
            float send = u3 ? v[i] : v[i + 2];
            float recv = __shfl_xor_sync(0xffffffffu, send, 16);
            v[i] = (u3 ? v[i + 2] : v[i]) + recv;
        }
        // this lane owns slot s; cols = base + (lane&3)*2 {, +1}
        int s = (u1 ? 4 : 0) | (u2 ? 2 : 0) | (u3 ? 1 : 0);
        int gc = col0 + warpN * 64 + (s >> 1) * 16 + (s & 1) * 8 + (lane & 3) * 2;
        atomicAdd(&g_pt[gc],     v[0]);
        atomicAdd(&g_pt[gc + 1], v[1]);
    }
}

__global__ void __launch_bounds__(128)
finalize_kernel(const int* __restrict__ label, float* __restrict__ out) {
    int i = blockIdx.x * blockDim.x + threadIdx.x;   // 64 x 128 = 8192
    int i0 = i & (NROWS - 1);
    float Ng   = g_pt[i];
    float term = log1pf(Ng / g_pos[i0]);      // == -log(pos/(Ng+pos))
    int   gs   = 2 * g_cnt[label[i0] & 63];
    float val  = term / (float)gs;
#pragma unroll
    for (int o = 16; o > 0; o >>= 1) val += __shfl_down_sync(0xffffffffu, val, o);
    __shared__ float ws[4];
    int lane = threadIdx.x & 31, w = threadIdx.x >> 5;
    if (lane == 0) ws[w] = val;
    __syncthreads();
    if (w == 0) {
        val = (lane < 4) ? ws[lane] : 0.f;
#pragma unroll
        for (int o = 2; o > 0; o >>= 1) val += __shfl_down_sync(0xffffffffu, val, o);
        if (lane == 0) atomicAdd(out, val);
    }
}

extern "C" void kernel_launch(void* const* d_in, const int* in_sizes, int n_in,
                              void* d_out, int out_size) {
    (void)in_sizes; (void)n_in; (void)out_size;
    const float* f1    = (const float*)d_in[0];
    const float* f2    = (const float*)d_in[1];
    const int*   label = (const int*)d_in[2];
    float*       out   = (float*)d_out;

    cudaFuncSetAttribute(sim_kernel, cudaFuncAttributeMaxDynamicSharedMemorySize, SMEM_BYTES);

    prep_kernel<<<257, 256>>>(f1, f2, label, out);
    sim_kernel<<<NPAIRS, 256, SMEM_BYTES>>>(label);
    finalize_kernel<<<64, 128>>>(label, out);
}

// round 16
// speedup vs baseline: 1.4198x; 1.4198x over previous
#include <cuda_runtime.h>
#include <cstdint>

#define NROWS 4096
#define TWO_N 8192
#define DDIM  64
#define BM 128
#define NPAIRS 2080            // 2016 strict upper pairs + 64 diagonal
#define NSTRICT 2016
#define INV_T 20.0f
#define PRESCALE 5.3715827f    // sqrt(20 * log2(e)); dot of scaled = ex2 exponent

// sim smem layout
#define OFF_A    0             // 128x64 bf16 swizzled (16KB)
#define OFF_B    16384         // 16KB
#define OFF_LABR 32768         // 128 ints
#define OFF_LABC 33280         // 128 ints
#define SMEM_BYTES 33792

__device__ __align__(128) uint2 g_feat[TWO_N * 16];   // prescaled bf16, 128B rows
__device__ float g_pt[TWO_N];                          // Ng partials (masked sums)
__device__ float g_pos[NROWS];
__device__ int   g_cnt[64];

static __device__ __forceinline__ uint32_t smem_u32(const void* p) {
    uint32_t a;
    asm("{ .reg .u64 t; cvta.to.shared.u64 t, %1; cvt.u32.u64 %0, t; }" : "=r"(a) : "l"(p));
    return a;
}
static __device__ __forceinline__ float ex2f(float x) {
    float r; asm("ex2.approx.f32 %0, %1;" : "=f"(r) : "f"(x)); return r;
}
static __device__ __forceinline__ uint32_t bf16pack(float lo, float hi) {
    uint32_t r; asm("cvt.rn.bf16x2.f32 %0, %1, %2;" : "=r"(r) : "f"(hi), "f"(lo)); return r;
}
static __device__ __forceinline__ void cpa16(uint32_t dst, const void* src) {
    asm volatile("cp.async.cg.shared.global [%0], [%1], 16;" :: "r"(dst), "l"(src));
}
#define CP_COMMIT() asm volatile("cp.async.commit_group;" ::: "memory")
#define CP_WAIT0()  asm volatile("cp.async.wait_group 0;" ::: "memory")

#define LDSM4(r0, r1, r2, r3, addr) \
    asm volatile("ldmatrix.sync.aligned.m8n8.x4.shared.b16 {%0,%1,%2,%3}, [%4];" \
                 : "=r"(r0), "=r"(r1), "=r"(r2), "=r"(r3) : "r"(addr))

#define MMA16816(d, a, b0, b1) \
    asm volatile("mma.sync.aligned.m16n8k16.row.col.f32.bf16.bf16.f32 " \
                 "{%0,%1,%2,%3}, {%4,%5,%6,%7}, {%8,%9}, {%0,%1,%2,%3};" \
                 : "+f"((d)[0]), "+f"((d)[1]), "+f"((d)[2]), "+f"((d)[3]) \
                 : "r"((a)[0]), "r"((a)[1]), "r"((a)[2]), "r"((a)[3]), "r"(b0), "r"(b1))

// ---- prep: blocks 0..255 convert 16 rows each, pos dots, zero g_pt slice;
//      block 256: hist + out zero ----
__global__ void __launch_bounds__(256)
prep_kernel(const float* __restrict__ f1, const float* __restrict__ f2,
            const int* __restrict__ label, float* __restrict__ out) {
    const int tid = threadIdx.x;
    const int b = blockIdx.x;
    if (b < 256) {
        int r = b * 16 + (tid >> 4);         // global row 0..4095
        int q = tid & 15;                    // float4 slot
        float4 v1 = ((const float4*)(f1 + r * DDIM))[q];
        float4 v2 = ((const float4*)(f2 + r * DDIM))[q];
        g_feat[r * 16 + q] =
            make_uint2(bf16pack(v1.x * PRESCALE, v1.y * PRESCALE),
                       bf16pack(v1.z * PRESCALE, v1.w * PRESCALE));
        g_feat[(r + NROWS) * 16 + q] =
            make_uint2(bf16pack(v2.x * PRESCALE, v2.y * PRESCALE),
                       bf16pack(v2.z * PRESCALE, v2.w * PRESCALE));
        float d = v1.x * v2.x + v1.y * v2.y + v1.z * v2.z + v1.w * v2.w;
        d += __shfl_xor_sync(0xffffffffu, d, 1);
        d += __shfl_xor_sync(0xffffffffu, d, 2);
        d += __shfl_xor_sync(0xffffffffu, d, 4);
        d += __shfl_xor_sync(0xffffffffu, d, 8);
        if (q == 0) g_pos[r] = __expf(d * INV_T);
        if (tid < 32) g_pt[b * 32 + tid] = 0.f;
    } else {
        __shared__ int h[64];
        if (tid < 64) h[tid] = 0;
        __syncthreads();
        for (int i = tid; i < NROWS; i += 256) atomicAdd(&h[label[i] & 63], 1);
        __syncthreads();
        if (tid < 64) g_cnt[tid] = h[tid];
        if (tid == 0) out[0] = 0.f;
    }
}

// ---- sim: strict pairs first; four 16-col strips (unroll 1, 4 CTAs/SM);
//      Ng-direct masked sums; per-strip shuffle col reduce ----
__global__ void __launch_bounds__(256, 4)
sim_kernel(const int* __restrict__ label) {
    extern __shared__ __align__(1024) char smem[];
    const uint32_t sb = smem_u32(smem);
    const int tid  = threadIdx.x;
    const int lane = tid & 31;
    const int wid  = tid >> 5;
    const int warpM = wid >> 1;
    const int warpN = wid & 1;

    // bid -> (ti, tj): strict pairs (ti<tj) for bid<2016, diagonal after
    const int t = blockIdx.x;
    int ti, tj;
    if (t < NSTRICT) {
        ti = (int)(63.5f - sqrtf(63.5f * 63.5f - 2.0f * (float)t));
        while (63 * ti - ti * (ti - 1) / 2 > t) ti--;
        while (63 * (ti + 1) - (ti + 1) * ti / 2 <= t) ti++;
        tj = ti + 1 + (t - (63 * ti - ti * (ti - 1) / 2));
    } else {
        ti = tj = t - NSTRICT;
    }
    const int row0 = ti * BM;
    const int col0 = tj * BM;
    const bool offdiag = (t < NSTRICT);

    // prologue: A (block ti), B (block tj), label slices
    {
        const char* gb = (const char*)g_feat;
#pragma unroll
        for (int it = 0; it < 4; it++) {
            int s = it * 256 + tid;
            int r = s >> 3, c = s & 7;
            uint32_t sw = (uint32_t)((c * 16) ^ ((r & 7) << 4));
            cpa16(sb + OFF_A + r * 128 + sw, gb + (size_t)(row0 + r) * 128 + c * 16);
            cpa16(sb + OFF_B + r * 128 + sw, gb + (size_t)(col0 + r) * 128 + c * 16);
        }
        if (tid < 32) cpa16(sb + OFF_LABR + tid * 16, label + (ti & 31) * 128 + tid * 4);
        else if (tid < 64) cpa16(sb + OFF_LABC + (tid - 32) * 16,
                                 label + (tj & 31) * 128 + (tid - 32) * 4);
        CP_COMMIT();
    }

    const int kaA = (lane >> 4) * 16;
    const int kbB = ((lane >> 3) & 1) * 16;

    CP_WAIT0();
    __syncthreads();

    const int* labr = (const int*)(smem + OFF_LABR);
    const int* labc = (const int*)(smem + OFF_LABC);
    int labR[4];
#pragma unroll
    for (int mb = 0; mb < 2; mb++)
#pragma unroll
        for (int h = 0; h < 2; h++)
            labR[mb * 2 + h] = labr[warpM * 32 + mb * 16 + (lane >> 2) + h * 8];

    float tot[4] = {0.f, 0.f, 0.f, 0.f};

#pragma unroll 1
    for (int qq = 0; qq < 4; qq++) {
        const int nbase = warpN * 64 + qq * 16;
        const int nn = nbase + (lane & 7) + ((lane >> 4) & 1) * 8;

        float acc[2][2][4];
#pragma unroll
        for (int mb = 0; mb < 2; mb++)
#pragma unroll
            for (int nb = 0; nb < 2; nb++)
#pragma unroll
                for (int e = 0; e < 4; e++) acc[mb][nb][e] = 0.f;

#pragma unroll
        for (int kc = 0; kc < 4; kc++) {
            uint32_t a[2][4];
#pragma unroll
            for (int mb = 0; mb < 2; mb++) {
                int rowA = warpM * 32 + mb * 16 + (lane & 7) + ((lane >> 3) & 1) * 8;
                uint32_t addr = sb + OFF_A + rowA * 128
                              + ((kc * 32 + kaA) ^ ((rowA & 7) << 4));
                LDSM4(a[mb][0], a[mb][1], a[mb][2], a[mb][3], addr);
            }
            uint32_t b0, b1, b2, b3;
            uint32_t addr = sb + OFF_B + nn * 128
                          + ((kc * 32 + kbB) ^ ((nn & 7) << 4));
            LDSM4(b0, b1, b2, b3, addr);
#pragma unroll
            for (int mb = 0; mb < 2; mb++) {
                MMA16816(acc[mb][0], a[mb], b0, b1);
                MMA16816(acc[mb][1], a[mb], b2, b3);
            }
        }

        // epilogue: exp + Ng-direct masked accumulation + per-strip col reduce
#pragma unroll
        for (int nb = 0; nb < 2; nb++) {
            int2 lb2 = *(const int2*)(labc + nbase + nb * 8 + (lane & 3) * 2);
            float c0 = 0.f, c1 = 0.f;
#pragma unroll
            for (int mb = 0; mb < 2; mb++)
#pragma unroll
                for (int h = 0; h < 2; h++) {
                    float e0 = ex2f(acc[mb][nb][2 * h]);
                    float e1 = ex2f(acc[mb][nb][2 * h + 1]);
                    float z0 = (lb2.x == labR[mb * 2 + h]) ? 0.f : e0;
                    float z1 = (lb2.y == labR[mb * 2 + h]) ? 0.f : e1;
                    tot[mb * 2 + h] += z0 + z1;
                    c0 += z0; c1 += z1;
                }
            if (offdiag) {
#pragma unroll
                for (int o = 4; o <= 16; o <<= 1) {
                    c0 += __shfl_xor_sync(0xffffffffu, c0, o);
                    c1 += __shfl_xor_sync(0xffffffffu, c1, o);
                }
                if ((lane >> 2) == 0) {
                    int gc = col0 + nbase + nb * 8 + (lane & 3) * 2;
                    atomicAdd(&g_pt[gc],     c0);
                    atomicAdd(&g_pt[gc + 1], c1);
                }
            }
        }
    }

    // row path: quad reduce + atomic add
#pragma unroll
    for (int i = 0; i < 4; i++) {
        float tv = tot[i];
        tv += __shfl_xor_sync(0xffffffffu, tv, 1);
        tv += __shfl_xor_sync(0xffffffffu, tv, 2);
        if ((lane & 3) == 0) {
            int grow = row0 + warpM * 32 + (i >> 1) * 16 + (lane >> 2) + (i & 1) * 8;
            atomicAdd(&g_pt[grow], tv);
        }
    }
}

__global__ void __launch_bounds__(128)
finalize_kernel(const int* __restrict__ label, float* __restrict__ out) {
    int i = blockIdx.x * blockDim.x + threadIdx.x;   // 64 x 128 = 8192
    int i0 = i & (NROWS - 1);
    float Ng   = g_pt[i];
    float term = log1pf(Ng / g_pos[i0]);      // == -log(pos/(Ng+pos))
    int   gs   = 2 * g_cnt[label[i0] & 63];
    float val  = term / (float)gs;
#pragma unroll
    for (int o = 16; o > 0; o >>= 1) val += __shfl_down_sync(0xffffffffu, val, o);
    __shared__ float ws[4];
    int lane = threadIdx.x & 31, w = threadIdx.x >> 5;
    if (lane == 0) ws[w] = val;
    __syncthreads();
    if (w == 0) {
        val = (lane < 4) ? ws[lane] : 0.f;
#pragma unroll
        for (int o = 2; o > 0; o >>= 1) val += __shfl_down_sync(0xffffffffu, val, o);
        if (lane == 0) atomicAdd(out, val);
    }
}

extern "C" void kernel_launch(void* const* d_in, const int* in_sizes, int n_in,
                              void* d_out, int out_size) {
    (void)in_sizes; (void)n_in; (void)out_size;
    const float* f1    = (const float*)d_in[0];
    const float* f2    = (const float*)d_in[1];
    const int*   label = (const int*)d_in[2];
    float*       out   = (float*)d_out;

    cudaFuncSetAttribute(sim_kernel, cudaFuncAttributeMaxDynamicSharedMemorySize, SMEM_BYTES);

    prep_kernel<<<257, 256>>>(f1, f2, label, out);
    sim_kernel<<<NPAIRS, 256, SMEM_BYTES>>>(label);
    finalize_kernel<<<64, 128>>>(label, out);
}